// round 2
// baseline (speedup 1.0000x reference)
#include <cuda_runtime.h>

namespace {
constexpr int H = 128, Wd = 128;
constexpr int PLANE = H * Wd;          // 16384
constexpr int NBLOCKS = 32 * 64;       // 2048 planes
constexpr int WARPS = 8;
constexpr int RPW = H / WARPS;         // 16 rows per warp
constexpr int TBL = 9 * 25;            // 225 WL entries
}

// s[] holds bin<<7 : byte offset with bq-stride 128 in the replicated table.
struct RowS {
    float x[6];   // [0]=left edge, [1..4]=own 4 cols, [5]=right edge
    int   s[6];
};

__device__ __forceinline__ float4 ldrow(const float* __restrict__ xp, int r,
                                        int lane) {
    float4 v = make_float4(0.f, 0.f, 0.f, 0.f);
    if ((unsigned)r < (unsigned)H)
        v = __ldg(reinterpret_cast<const float4*>(xp + r * Wd + lane * 4));
    return v;
}

// Quantize + edge exchange. Input value was loaded an iteration earlier, so
// the dependent SHFLs here are not latency-exposed.
__device__ __forceinline__ void build(float4 v, int lane, RowS& R) {
    R.x[1] = v.x; R.x[2] = v.y; R.x[3] = v.z; R.x[4] = v.w;
#pragma unroll
    for (int i = 1; i <= 4; ++i) {
        float t = fminf(R.x[i] * 5.0f, 4.0f);   // x>=0; floor==trunc
        R.s[i] = ((int)t) << 7;
    }
    R.x[0] = __shfl_up_sync(0xffffffffu, v.w, 1);
    R.s[0] = __shfl_up_sync(0xffffffffu, R.s[4], 1);
    R.x[5] = __shfl_down_sync(0xffffffffu, v.x, 1);
    R.s[5] = __shfl_down_sync(0xffffffffu, R.s[1], 1);
    if (lane == 0)  R.x[0] = 0.f;   // s stays in-bounds; x=0 kills the term
    if (lane == 31) R.x[5] = 0.f;
}

__global__ __launch_bounds__(256, 4)
void col_kernel(const float* __restrict__ x,
                const float* __restrict__ Wp,
                const float* __restrict__ Lp,
                float* __restrict__ out) {
    // Bank-replicated WL table: addr = (o*25 + bp*5 + bq)*128 + lane*4.
    // Lane l only ever touches bank l -> conflict-free LDS.
    __shared__ float sWL[TBL * 32];

    for (int t = threadIdx.x; t < TBL * 32; t += 256) {
        int idx = t >> 5;               // o*25 + bp*5 + bq
        int o  = idx / 25;
        int r  = idx - o * 25;
        int bp = r / 5;
        int bq = r - bp * 5;
        sWL[t] = Wp[o] * Lp[bq * 5 + bp];
    }
    __syncthreads();

    const int plane = blockIdx.x;
    const float* xp = x + (size_t)plane * PLANE;
    float* op = out + (size_t)plane * PLANE;

    const int lane = threadIdx.x & 31;
    const int warp = threadIdx.x >> 5;
    const int r0 = warp * RPW;
    const char* laneBase = reinterpret_cast<const char*>(sWL) + lane * 4;

    RowS A, Bc, Cn;
    build(ldrow(xp, r0 - 1, lane), lane, A);
    build(ldrow(xp, r0,     lane), lane, Bc);
    float4 v_next = ldrow(xp, r0 + 1, lane);   // prefetch one row ahead

#pragma unroll 4
    for (int r = r0; r < r0 + RPW; ++r) {
        float4 v_follow = ldrow(xp, r + 2, lane);   // issue next prefetch first
        build(v_next, lane, Cn);                    // value loaded last iter

        float res[4];
#pragma unroll
        for (int i = 0; i < 4; ++i) {
            // base = laneBase + bp*640  (one IMAD: s[i+1]*5 + laneBase)
            const char* pb = laneBase + Bc.s[i + 1] * 5;
            float s = 0.f;
            // addr = pb + bq*128 + o*3200  -> IADD3 + LDS + FFMA per term
#define COL_TERM(R, dh, dw)                                                    \
            s += *reinterpret_cast<const float*>(                              \
                     pb + (R).s[i + (dw)] + ((dh)*3 + (dw)) * 3200)            \
                 * (R).x[i + (dw)];
            COL_TERM(A,  0, 0) COL_TERM(A,  0, 1) COL_TERM(A,  0, 2)
            COL_TERM(Bc, 1, 0) COL_TERM(Bc, 1, 1) COL_TERM(Bc, 1, 2)
            COL_TERM(Cn, 2, 0) COL_TERM(Cn, 2, 1) COL_TERM(Cn, 2, 2)
#undef COL_TERM
            res[i] = s;
        }

        *reinterpret_cast<float4*>(op + r * Wd + lane * 4) =
            make_float4(res[0], res[1], res[2], res[3]);

        A = Bc;
        Bc = Cn;
        v_next = v_follow;
    }
}

extern "C" void kernel_launch(void* const* d_in, const int* in_sizes, int n_in,
                              void* d_out, int out_size) {
    const float* x = nullptr;
    const float* W = nullptr;
    const float* L = nullptr;
    for (int i = 0; i < n_in; ++i) {
        if (in_sizes[i] == 9)       W = (const float*)d_in[i];
        else if (in_sizes[i] == 25) L = (const float*)d_in[i];
        else                        x = (const float*)d_in[i];
    }
    col_kernel<<<NBLOCKS, 256>>>(x, W, L, (float*)d_out);
}

// round 3
// speedup vs baseline: 1.1066x; 1.1066x over previous
#include <cuda_runtime.h>

namespace {
constexpr int H = 128, Wd = 128;
constexpr int PLANE = H * Wd;          // 16384
constexpr int NBLOCKS = 32 * 64;       // 2048 planes
constexpr int RPW = 16;                // rows per warp (8 warps)
constexpr int TBL = 9 * 25;            // 225 WL entries
}

struct RowS {
    float x[6];   // [0]=left edge, [1..4]=own 4 cols, [5]=right edge
    int   b[6];   // bins
};

__device__ __forceinline__ float4 ldrow(const float* __restrict__ xp, int r,
                                        int lane) {
    float4 v = make_float4(0.f, 0.f, 0.f, 0.f);
    if ((unsigned)r < (unsigned)H)
        v = __ldg(reinterpret_cast<const float4*>(xp + r * Wd + lane * 4));
    return v;
}

// Quantize + edge exchange. The raw value was loaded an iteration earlier,
// so the dependent cvt/SHFLs here are not LDG-latency-exposed.
__device__ __forceinline__ void build(float4 v, int lane, RowS& R) {
    R.x[1] = v.x; R.x[2] = v.y; R.x[3] = v.z; R.x[4] = v.w;
#pragma unroll
    for (int i = 1; i <= 4; ++i)
        R.b[i] = (int)fminf(R.x[i] * 5.0f, 4.0f);   // x>=0; floor==trunc
    R.x[0] = __shfl_up_sync(0xffffffffu, v.w, 1);
    R.b[0] = __shfl_up_sync(0xffffffffu, R.b[4], 1);
    R.x[5] = __shfl_down_sync(0xffffffffu, v.x, 1);
    R.b[5] = __shfl_down_sync(0xffffffffu, R.b[1], 1);
    if (lane == 0)  R.x[0] = 0.f;   // x=0 kills the term; b irrelevant
    if (lane == 31) R.x[5] = 0.f;
}

__global__ __launch_bounds__(256, 4)
void col_kernel(const float* __restrict__ x,
                const float* __restrict__ Wp,
                const float* __restrict__ Lp,
                float* __restrict__ out) {
    // Bank-replicated WL table: addr/4 = lane + bp*32 + bq*160 + o*800.
    // Lane l only ever touches bank l -> conflict-free LDS.
    __shared__ float sWL[TBL * 32];

    for (int t = threadIdx.x; t < TBL * 32; t += 256) {
        int idx = t >> 5;               // o*25 + bq*5 + bp
        int o  = idx / 25;
        int i  = idx - o * 25;          // bq*5 + bp, matches L row-major
        sWL[t] = Wp[o] * Lp[i];
    }
    __syncthreads();

    const int plane = blockIdx.x;
    const float* xp = x + (size_t)plane * PLANE;
    float* op = out + (size_t)plane * PLANE;

    const int lane = threadIdx.x & 31;
    const int warp = threadIdx.x >> 5;
    const int r0 = warp * RPW;
    const char* laneBase = reinterpret_cast<const char*>(sWL) + lane * 4;

    RowS Rr[3];
    float4 wv[2];
    build(ldrow(xp, r0 - 1, lane), lane, Rr[0]);
    build(ldrow(xp, r0,     lane), lane, Rr[1]);
    wv[0] = ldrow(xp, r0 + 1, lane);

#pragma unroll
    for (int k = 0; k < RPW; ++k) {
        const int r = r0 + k;
        wv[(k + 1) & 1] = ldrow(xp, r + 2, lane);   // prefetch (OOB -> zeros)
        build(wv[k & 1], lane, Rr[(k + 2) % 3]);    // loaded last iteration

        const RowS& A  = Rr[k % 3];
        const RowS& Bc = Rr[(k + 1) % 3];
        const RowS& Cn = Rr[(k + 2) % 3];

        float res[4];
#pragma unroll
        for (int i = 0; i < 4; ++i) {
            // pb = laneBase + bp*128 ; per term IMAD(bq,640,pb) + LDS[R+o*3200]
            const char* pb = laneBase + Bc.b[i + 1] * 128;
            float s = 0.f;
#define COL_TERM(R, dh, dw)                                                    \
            s += *reinterpret_cast<const float*>(                              \
                     pb + (R).b[i + (dw)] * 640 + ((dh)*3 + (dw)) * 3200)      \
                 * (R).x[i + (dw)];
            COL_TERM(A,  0, 0) COL_TERM(A,  0, 1) COL_TERM(A,  0, 2)
            COL_TERM(Bc, 1, 0) COL_TERM(Bc, 1, 1) COL_TERM(Bc, 1, 2)
            COL_TERM(Cn, 2, 0) COL_TERM(Cn, 2, 1) COL_TERM(Cn, 2, 2)
#undef COL_TERM
            res[i] = s;
        }

        *reinterpret_cast<float4*>(op + r * Wd + lane * 4) =
            make_float4(res[0], res[1], res[2], res[3]);
    }
}

extern "C" void kernel_launch(void* const* d_in, const int* in_sizes, int n_in,
                              void* d_out, int out_size) {
    const float* x = nullptr;
    const float* W = nullptr;
    const float* L = nullptr;
    for (int i = 0; i < n_in; ++i) {
        if (in_sizes[i] == 9)       W = (const float*)d_in[i];
        else if (in_sizes[i] == 25) L = (const float*)d_in[i];
        else                        x = (const float*)d_in[i];
    }
    col_kernel<<<NBLOCKS, 256>>>(x, W, L, (float*)d_out);
}